// round 14
// baseline (speedup 1.0000x reference)
#include <cuda_runtime.h>
#include <cuda_fp16.h>
#include <cstdint>
#include <math.h>

#define E  4096
#define Hh 32
#define Mm 256
#define Bb 8
#define Nn 256
#define Dd 128

// ---------------- scratch (alloc-free: __device__ globals) ----------------
__device__ float g_attn[Bb * Hh * Mm * Nn];   // fp32 scores S

// fp16 hi/lo planes
__device__ __half g_qh[Mm * E],        g_ql[Mm * E];
__device__ __half g_kvh[Bb * Nn * E],  g_kvl[Bb * Nn * E];
__device__ __half g_kvph[Bb * Nn * E], g_kvpl[Bb * Nn * E];
__device__ __half g_Qh[Mm * E],        g_Ql[Mm * E];
__device__ __half g_Kh[Bb * Nn * E],   g_Kl[Bb * Nn * E];
__device__ __half g_Vh[Bb * Nn * E],   g_Vl[Bb * Nn * E];
__device__ __half g_Vth[Bb * Hh * Dd * Nn], g_Vtl[Bb * Hh * Dd * Nn];
__device__ __half g_Ph[Bb * Hh * Mm * Nn],  g_Pl[Bb * Hh * Mm * Nn];
__device__ __half g_oh[Bb * Mm * E];
__device__ __half g_wh[4ULL * E * E];   // Wq,Wk,Wv,Wo hi planes

// ---------------- helpers ----------------
__device__ __forceinline__ uint32_t smem_u32(const void* p) {
    uint32_t a;
    asm("{ .reg .u64 t; cvta.to.shared.u64 t, %1; cvt.u32.u64 %0, t; }"
        : "=r"(a) : "l"(p));
    return a;
}

__device__ __forceinline__ void cp_async16(uint32_t dst, const void* src) {
    asm volatile("cp.async.cg.shared.global [%0], [%1], 16;"
                 :: "r"(dst), "l"(src) : "memory");
}
#define CP_COMMIT() asm volatile("cp.async.commit_group;" ::: "memory")
#define CP_WAIT1()  asm volatile("cp.async.wait_group 1;" ::: "memory")

__device__ __forceinline__ void mma16816(float* d, const uint32_t* a, const uint32_t* b) {
    asm volatile(
        "mma.sync.aligned.m16n8k16.row.col.f32.f16.f16.f32 "
        "{%0,%1,%2,%3}, {%4,%5,%6,%7}, {%8,%9}, {%0,%1,%2,%3};"
        : "+f"(d[0]), "+f"(d[1]), "+f"(d[2]), "+f"(d[3])
        : "r"(a[0]), "r"(a[1]), "r"(a[2]), "r"(a[3]), "r"(b[0]), "r"(b[1]));
}

__device__ __forceinline__ void ldsm4(uint32_t& r0, uint32_t& r1, uint32_t& r2, uint32_t& r3,
                                      uint32_t addr) {
    asm volatile("ldmatrix.sync.aligned.m8n8.x4.shared.b16 {%0,%1,%2,%3}, [%4];"
                 : "=r"(r0), "=r"(r1), "=r"(r2), "=r"(r3) : "r"(addr));
}

__device__ __forceinline__ void split_f4(float4 v, uint2& hi, uint2& lo) {
    __half2 h0 = __floats2half2_rn(v.x, v.y);
    __half2 h1 = __floats2half2_rn(v.z, v.w);
    float2 f0 = __half22float2(h0), f1 = __half22float2(h1);
    __half2 l0 = __floats2half2_rn(v.x - f0.x, v.y - f0.y);
    __half2 l1 = __floats2half2_rn(v.z - f1.x, v.w - f1.y);
    hi.x = *(uint32_t*)&h0; hi.y = *(uint32_t*)&h1;
    lo.x = *(uint32_t*)&l0; lo.y = *(uint32_t*)&l1;
}

__device__ __forceinline__ void split2(float x, float y, uint32_t& h, uint32_t& l) {
    __half2 hh = __floats2half2_rn(x, y);
    float2 f = __half22float2(hh);
    __half2 ll = __floats2half2_rn(x - f.x, y - f.y);
    h = *(uint32_t*)&hh; l = *(uint32_t*)&ll;
}

// ---------------- merged weight split, MLP=4 ----------------
__global__ void __launch_bounds__(256) split_all_kernel(
    const float* __restrict__ in_w, const float* __restrict__ out_w,
    __half* __restrict__ wh)
{
    const size_t n_in = 3ULL * E * E / 4;
    size_t base = (size_t)blockIdx.x * 1024 + threadIdx.x;
    float4 v[4];
#pragma unroll
    for (int j = 0; j < 4; j++) {
        size_t i = base + j * 256;
        v[j] = (i < n_in) ? ((const float4*)in_w)[i]
                          : ((const float4*)out_w)[i - n_in];
    }
#pragma unroll
    for (int j = 0; j < 4; j++) {
        size_t i = base + j * 256;
        __half2 h0 = __floats2half2_rn(v[j].x, v[j].y);
        __half2 h1 = __floats2half2_rn(v[j].z, v[j].w);
        uint2 h;
        h.x = *(uint32_t*)&h0; h.y = *(uint32_t*)&h1;
        *(uint2*)(wh + i * 4) = h;
    }
}

// ---------------- merged LayerNorm ----------------
__global__ void __launch_bounds__(256) ln_all(
    const float* __restrict__ x, const float* __restrict__ query,
    const float* __restrict__ pos,
    const float* __restrict__ kv_w, const float* __restrict__ kv_b,
    const float* __restrict__ q_w,  const float* __restrict__ q_b,
    __half* __restrict__ kvh, __half* __restrict__ kvl,
    __half* __restrict__ kvph, __half* __restrict__ kvpl,
    __half* __restrict__ qh, __half* __restrict__ ql)
{
    int row = blockIdx.x;
    int tid = threadIdx.x;
    const bool isq = row >= Bb * Nn;
    int r = isq ? row - Bb * Nn : row;
    const float* src = isq ? query + (size_t)r * E : x + (size_t)r * E;
    const float* w  = isq ? q_w : kv_w;
    const float* bs = isq ? q_b : kv_b;
    __half* h0 = isq ? nullptr : kvh + (size_t)r * E;
    __half* l0 = isq ? nullptr : kvl + (size_t)r * E;
    __half* hp = (isq ? qh : kvph) + (size_t)r * E;
    __half* lp = (isq ? ql : kvpl) + (size_t)r * E;
    int prow = isq ? r : (r & (Nn - 1));

    const float4* xr = (const float4*)src;
    float4 v[4];
    float s = 0.f, sq = 0.f;
#pragma unroll
    for (int i = 0; i < 4; i++) {
        v[i] = xr[tid + 256 * i];
        s  += v[i].x + v[i].y + v[i].z + v[i].w;
        sq += v[i].x * v[i].x + v[i].y * v[i].y + v[i].z * v[i].z + v[i].w * v[i].w;
    }
    __shared__ float s1[256], s2[256];
    s1[tid] = s; s2[tid] = sq;
    __syncthreads();
    for (int st = 128; st > 0; st >>= 1) {
        if (tid < st) { s1[tid] += s1[tid + st]; s2[tid] += s2[tid + st]; }
        __syncthreads();
    }
    float mean = s1[0] * (1.f / E);
    float var  = s2[0] * (1.f / E) - mean * mean;
    float rstd = rsqrtf(var + 1e-5f);

    const float4* wr = (const float4*)w;
    const float4* br = (const float4*)bs;
    const float4* pr = (const float4*)(pos + (size_t)prow * E);
#pragma unroll
    for (int i = 0; i < 4; i++) {
        int c = tid + 256 * i;
        float4 ww = wr[c], bb = br[c];
        float4 o;
        o.x = (v[i].x - mean) * rstd * ww.x + bb.x;
        o.y = (v[i].y - mean) * rstd * ww.y + bb.y;
        o.z = (v[i].z - mean) * rstd * ww.z + bb.z;
        o.w = (v[i].w - mean) * rstd * ww.w + bb.w;
        size_t off = (size_t)c * 4;
        uint2 h, l;
        if (h0) {
            split_f4(o, h, l);
            *(uint2*)(h0 + off) = h;
            *(uint2*)(l0 + off) = l;
        }
        float4 p = pr[c];
        o.x += p.x; o.y += p.y; o.z += p.z; o.w += p.w;
        split_f4(o, h, l);
        *(uint2*)(hp + off) = h;
        *(uint2*)(lp + off) = l;
    }
}

// ======================= pipelined HMMA GEMM body, 256x128 tile, ldmatrix, warp 64x64 =======================
// fp32 accumulate. NPASS=1: Ah.Bh ; 2: +Al.Bh ; 3: +Ah.Bl.
// stage layout: Ah@0 (32K), [Al@32K], Bh@(NPASS>=2?64K:32K) (16K), [Bl@+16K]. 2 stages.
#define BK 64
#define A32 32768
#define P16 16384

template <int NPASS>
__device__ __forceinline__ void gemm_body(
    const __half* p0, const __half* p1,
    const __half* p2, const __half* p3,
    const float* bptr, float scale,
    float* ocf, __half* och, __half* ocl, size_t cOff,
    int lda, int ldb, int ldc, int NIT, int m0, int n0, char* sm)
{
    constexpr uint32_t BOFF  = (NPASS >= 2) ? 2 * A32 : A32;
    constexpr uint32_t STAGE = BOFF + ((NPASS == 3) ? 2 * P16 : P16);
    const uint32_t sbase = smem_u32(sm);
    const int tid  = threadIdx.x;
    const int wid  = tid >> 5;
    const int lane = tid & 31;
    const int g    = lane >> 2;
    const int tq   = lane & 3;
    const int wm   = (wid >> 1) * 64;   // 4 warps along M (64 rows)
    const int wn   = (wid & 1) * 64;    // 2 warps along N

    // ldmatrix per-thread address components
    const int hiA  = lane >> 4;                 // A k-half select
    uint32_t rAterm[4], rA7[4];
#pragma unroll
    for (int mt = 0; mt < 4; mt++) {
        int rowA = wm + mt * 16 + (lane & 15);
        rAterm[mt] = (uint32_t)rowA * 128;
        rA7[mt]    = (uint32_t)(rowA & 7);
    }
    const int khiB = (lane >> 3) & 1;           // B k-half select
    uint32_t rBterm[4], rB7[4];
#pragma unroll
    for (int j = 0; j < 4; j++) {
        int rowB = wn + (2 * j + (lane >> 4)) * 8 + (lane & 7);
        rBterm[j] = (uint32_t)rowB * 128;
        rB7[j]    = (uint32_t)(rowB & 7);
    }

    float acc[4][8][4];
#pragma unroll
    for (int i = 0; i < 4; i++)
#pragma unroll
        for (int j = 0; j < 8; j++)
#pragma unroll
            for (int k = 0; k < 4; k++) acc[i][j][k] = 0.f;

    auto issue = [&](int slot, int kt) {
        uint32_t sb = sbase + slot * STAGE;
#pragma unroll
        for (int j = 0; j < 8; j++) {      // A planes: 256 rows x 8 chunks
            int idx = tid + 256 * j;
            int row = idx >> 3;
            int c   = idx & 7;
            uint32_t so = row * 128 + ((c ^ (row & 7)) << 4);
            cp_async16(sb + so, p0 + (size_t)row * lda + kt + c * 8);
            if (NPASS >= 2)
                cp_async16(sb + A32 + so, p1 + (size_t)row * lda + kt + c * 8);
        }
#pragma unroll
        for (int j = 0; j < 4; j++) {      // B planes: 128 rows
            int idx = tid + 256 * j;
            int row = idx >> 3;
            int c   = idx & 7;
            uint32_t so = row * 128 + ((c ^ (row & 7)) << 4);
            cp_async16(sb + BOFF + so, p2 + (size_t)row * ldb + kt + c * 8);
            if (NPASS == 3)
                cp_async16(sb + BOFF + P16 + so, p3 + (size_t)row * ldb + kt + c * 8);
        }
    };

    issue(0, 0);  CP_COMMIT();
    if (NIT > 1) issue(1, BK);
    CP_COMMIT();

    for (int it = 0; it < NIT; it++) {
        CP_WAIT1();
        __syncthreads();

        const uint32_t base = sbase + (it & 1) * STAGE;
        const uint32_t AhB = base;
        const uint32_t AlB = base + A32;
        const uint32_t BhB = base + BOFF;
        const uint32_t BlB = base + BOFF + P16;
#pragma unroll
        for (int ks = 0; ks < BK; ks += 16) {
            const uint32_t kb = (uint32_t)(ks >> 3);
            uint32_t ah[4][4], bf[8][2];
#pragma unroll
            for (int mt = 0; mt < 4; mt++)
                ldsm4(ah[mt][0], ah[mt][1], ah[mt][2], ah[mt][3],
                      AhB + rAterm[mt] + (((kb + hiA) ^ rA7[mt]) << 4));
#pragma unroll
            for (int j = 0; j < 4; j++)
                ldsm4(bf[2 * j][0], bf[2 * j][1], bf[2 * j + 1][0], bf[2 * j + 1][1],
                      BhB + rBterm[j] + (((kb + khiB) ^ rB7[j]) << 4));
#pragma unroll
            for (int mt = 0; mt < 4; mt++)
#pragma unroll
                for (int nt = 0; nt < 8; nt++) mma16816(acc[mt][nt], ah[mt], bf[nt]);
            if (NPASS >= 2) {
                uint32_t al[4][4];
#pragma unroll
                for (int mt = 0; mt < 4; mt++)
                    ldsm4(al[mt][0], al[mt][1], al[mt][2], al[mt][3],
                          AlB + rAterm[mt] + (((kb + hiA) ^ rA7[mt]) << 4));
#pragma unroll
                for (int mt = 0; mt < 4; mt++)
#pragma unroll
                    for (int nt = 0; nt < 8; nt++) mma16816(acc[mt][nt], al[mt], bf[nt]);
            }
            if (NPASS == 3) {
#pragma unroll
                for (int j = 0; j < 4; j++)
                    ldsm4(bf[2 * j][0], bf[2 * j][1], bf[2 * j + 1][0], bf[2 * j + 1][1],
                          BlB + rBterm[j] + (((kb + khiB) ^ rB7[j]) << 4));
#pragma unroll
                for (int mt = 0; mt < 4; mt++)
#pragma unroll
                    for (int nt = 0; nt < 8; nt++) mma16816(acc[mt][nt], ah[mt], bf[nt]);
            }
        }
        __syncthreads();
        if (it + 2 < NIT) issue((it + 2) & 1, (it + 2) * BK);
        CP_COMMIT();
    }

    // epilogue
    float bn[8][2];
#pragma unroll
    for (int nt = 0; nt < 8; nt++) {
        if (bptr) {
            int n = n0 + wn + nt * 8 + tq * 2;
            bn[nt][0] = bptr[n];
            bn[nt][1] = bptr[n + 1];
        } else {
            bn[nt][0] = 0.f; bn[nt][1] = 0.f;
        }
    }
#pragma unroll
    for (int mt = 0; mt < 4; mt++)
#pragma unroll
        for (int half = 0; half < 2; half++) {
            int m = m0 + wm + mt * 16 + g + half * 8;
#pragma unroll
            for (int nt = 0; nt < 8; nt++) {
                float vx = acc[mt][nt][half * 2 + 0] * scale + bn[nt][0];
                float vy = acc[mt][nt][half * 2 + 1] * scale + bn[nt][1];
                size_t off = cOff + (size_t)m * ldc + n0 + wn + nt * 8 + tq * 2;
                if (ocf) *(float2*)(ocf + off) = make_float2(vx, vy);
                if (och) {
                    uint32_t h, l;
                    split2(vx, vy, h, l);
                    *(uint32_t*)(och + off) = h;
                    if (ocl) *(uint32_t*)(ocl + off) = l;
                }
            }
        }
}

#define SMEM_NP1 (2 * (A32 + P16))            //  96 KB
#define SMEM_NP2 (2 * (2 * A32 + P16))        // 160 KB
#define SMEM_NP3 (2 * (2 * A32 + 2 * P16))    // 192 KB

// ---------------- merged K/Q/V projection launch ----------------
// y<8: K (2-pass, 256-row tiles); y==8: Q (2-pass); y>=9: V (1-pass).
__global__ void __launch_bounds__(256, 1) proj_kernel(
    const __half* __restrict__ kvph, const __half* __restrict__ kvpl,
    const __half* __restrict__ qh,   const __half* __restrict__ ql,
    const __half* __restrict__ kvh,  const __half* __restrict__ kvl,
    const __half* __restrict__ wh,   const float* __restrict__ in_b,
    __half* __restrict__ Kh, __half* __restrict__ Kl,
    __half* __restrict__ Qh, __half* __restrict__ Ql,
    __half* __restrict__ Vh, __half* __restrict__ Vl)
{
    extern __shared__ char sm[];
    const int y = blockIdx.y;
    const int n0 = blockIdx.x * 128;
    if (y < 8) {
        int m0 = y * 256;
        gemm_body<2>(kvph + (size_t)m0 * E, kvpl + (size_t)m0 * E,
                     wh + (size_t)E * E + (size_t)n0 * E, nullptr,
                     in_b + E, 1.f, nullptr, Kh, Kl, 0,
                     E, E, E, E / BK, m0, n0, sm);
    } else if (y == 8) {
        gemm_body<2>(qh, ql,
                     wh + (size_t)n0 * E, nullptr,
                     in_b, 1.f, nullptr, Qh, Ql, 0,
                     E, E, E, E / BK, 0, n0, sm);
    } else {
        int m0 = (y - 9) * 256;
        gemm_body<1>(kvh + (size_t)m0 * E, nullptr,
                     wh + 2ULL * E * E + (size_t)n0 * E, nullptr,
                     in_b + 2 * E, 1.f, nullptr, Vh, Vl, 0,
                     E, E, E, E / BK, m0, n0, sm);
    }
}

// ---------------- generic batched GEMM ----------------
template <int NPASS>
__global__ void __launch_bounds__(256, 1) gemm_b(
    const __half* __restrict__ Ahp, const __half* __restrict__ Alp,
    const __half* __restrict__ Bhp, const __half* __restrict__ Blp,
    const float* __restrict__ bias, float scale,
    float* __restrict__ Cf, __half* __restrict__ Ch, __half* __restrict__ Cl,
    size_t aSH, size_t aSB, size_t bSH, size_t bSB, size_t cSH, size_t cSB,
    int lda, int ldb, int ldc, int NIT)
{
    extern __shared__ char sm[];
    const int m0 = blockIdx.y * 256;
    const int n0 = blockIdx.x * 128;
    const int z  = blockIdx.z;
    const int hz = z & 31, bz = z >> 5;
    const size_t aOff = (size_t)hz * aSH + (size_t)bz * aSB;
    const size_t bOff = (size_t)hz * bSH + (size_t)bz * bSB;
    const size_t cOff = (size_t)hz * cSH + (size_t)bz * cSB;
    gemm_body<NPASS>(
        Ahp + aOff + (size_t)m0 * lda,
        (NPASS >= 2) ? Alp + aOff + (size_t)m0 * lda : nullptr,
        Bhp + bOff + (size_t)n0 * ldb,
        (NPASS == 3) ? Blp + bOff + (size_t)n0 * ldb : nullptr,
        bias, scale, Cf, Ch, Cl, cOff, lda, ldb, ldc, NIT, m0, n0, sm);
}

// ---------------- V planes -> V^T planes per (b,h) ----------------
__global__ void __launch_bounds__(256) vtrans(
    const __half* __restrict__ Vh, const __half* __restrict__ Vl,
    __half* __restrict__ Vth, __half* __restrict__ Vtl)
{
    __shared__ __half t0[32][33], t1[32][33];
    int z = blockIdx.z;
    int hz = z & 31, bz = z >> 5;
    int d0 = blockIdx.x * 32;
    int n0 = blockIdx.y * 32;
    int tx = threadIdx.x & 31, ty = threadIdx.x >> 5;
#pragma unroll
    for (int i = 0; i < 4; i++) {
        int n = n0 + ty + i * 8;
        size_t src = ((size_t)bz * Nn + n) * E + hz * Dd + d0 + tx;
        t0[ty + i * 8][tx] = Vh[src];
        t1[ty + i * 8][tx] = Vl[src];
    }
    __syncthreads();
#pragma unroll
    for (int i = 0; i < 4; i++) {
        int d = d0 + ty + i * 8;
        size_t dst = ((size_t)z * Dd + d) * Nn + n0 + tx;
        Vth[dst] = t0[tx][ty + i * 8];
        Vtl[dst] = t1[tx][ty + i * 8];
    }
}

// ---------------- fused softmax + P-split + head-mean ----------------
__global__ void __launch_bounds__(256) softmax_mean(
    const float* __restrict__ attn,
    __half* __restrict__ Ph, __half* __restrict__ Pl,
    float* __restrict__ out_mean)
{
    __shared__ float red[8 * 256];
    int bm = blockIdx.x;
    int b = bm >> 8, m = bm & 255;
    int w = threadIdx.x >> 5, lane = threadIdx.x & 31;

    float ms[8];
#pragma unroll
    for (int i = 0; i < 8; i++) ms[i] = 0.f;

#pragma unroll
    for (int j = 0; j < 4; j++) {
        int h = w + j * 8;
        size_t row = ((size_t)(b * Hh + h) * Mm + m);
        const float4* p = (const float4*)(attn + row * Nn);
        float4 v0 = p[lane];
        float4 v1 = p[lane + 32];
        float mx = fmaxf(fmaxf(fmaxf(v0.x, v0.y), fmaxf(v0.z, v0.w)),
                         fmaxf(fmaxf(v1.x, v1.y), fmaxf(v1.z, v1.w)));
#pragma unroll
        for (int o = 16; o; o >>= 1) mx = fmaxf(mx, __shfl_xor_sync(0xffffffffu, mx, o));
        v0.x = expf(v0.x - mx); v0.y = expf(v0.y - mx);
        v0.z = expf(v0.z - mx); v0.w = expf(v0.w - mx);
        v1.x = expf(v1.x - mx); v1.y = expf(v1.y - mx);
        v1.z = expf(v1.z - mx); v1.w = expf(v1.w - mx);
        float s = v0.x + v0.y + v0.z + v0.w + v1.x + v1.y + v1.z + v1.w;
#pragma unroll
        for (int o = 16; o; o >>= 1) s += __shfl_xor_sync(0xffffffffu, s, o);
        float inv = 1.f / s;
        v0.x *= inv; v0.y *= inv; v0.z *= inv; v0.w *= inv;
        v1.x *= inv; v1.y *= inv; v1.z *= inv; v1.w *= inv;
        uint2 hh, ll;
        split_f4(v0, hh, ll);
        *(uint2*)(Ph + row * Nn + lane * 4) = hh;
        *(uint2*)(Pl + row * Nn + lane * 4) = ll;
        split_f4(v1, hh, ll);
        *(uint2*)(Ph + row * Nn + 128 + lane * 4) = hh;
        *(uint2*)(Pl + row * Nn + 128 + lane * 4) = ll;
        ms[0] += v0.x; ms[1] += v0.y; ms[2] += v0.z; ms[3] += v0.w;
        ms[4] += v1.x; ms[5] += v1.y; ms[6] += v1.z; ms[7] += v1.w;
    }
#pragma unroll
    for (int k = 0; k < 4; k++) red[w * 256 + lane * 4 + k]       = ms[k];
#pragma unroll
    for (int k = 0; k < 4; k++) red[w * 256 + 128 + lane * 4 + k] = ms[4 + k];
    __syncthreads();
    int n = threadIdx.x;
    float s = 0.f;
#pragma unroll
    for (int ww = 0; ww < 8; ww++) s += red[ww * 256 + n];
    out_mean[(size_t)bm * Nn + n] = s * (1.f / Hh);
}

// ---------------- launcher ----------------
extern "C" void kernel_launch(void* const* d_in, const int* in_sizes, int n_in,
                              void* d_out, int out_size)
{
    const float* x       = (const float*)d_in[0];
    const float* query   = (const float*)d_in[1];
    const float* pos     = (const float*)d_in[2];
    const float* ln_q_w  = (const float*)d_in[3];
    const float* ln_q_b  = (const float*)d_in[4];
    const float* ln_kv_w = (const float*)d_in[5];
    const float* ln_kv_b = (const float*)d_in[6];
    const float* in_w    = (const float*)d_in[7];
    const float* in_b    = (const float*)d_in[8];
    const float* out_w   = (const float*)d_in[9];
    const float* out_b   = (const float*)d_in[10];
    float* out = (float*)d_out;

    float *attn;
    cudaGetSymbolAddress((void**)&attn, g_attn);
    __half *qh, *ql, *kvh, *kvl, *kvph, *kvpl;
    __half *Qh, *Ql, *Kh, *Kl, *Vh, *Vl, *Vth, *Vtl, *Ph, *Pl, *oh, *wh;
    cudaGetSymbolAddress((void**)&qh,   g_qh);
    cudaGetSymbolAddress((void**)&ql,   g_ql);
    cudaGetSymbolAddress((void**)&kvh,  g_kvh);
    cudaGetSymbolAddress((void**)&kvl,  g_kvl);
    cudaGetSymbolAddress((void**)&kvph, g_kvph);
    cudaGetSymbolAddress((void**)&kvpl, g_kvpl);
    cudaGetSymbolAddress((void**)&Qh,   g_Qh);
    cudaGetSymbolAddress((void**)&Ql,   g_Ql);
    cudaGetSymbolAddress((void**)&Kh,   g_Kh);
    cudaGetSymbolAddress((void**)&Kl,   g_Kl);
    cudaGetSymbolAddress((void**)&Vh,   g_Vh);
    cudaGetSymbolAddress((void**)&Vl,   g_Vl);
    cudaGetSymbolAddress((void**)&Vth,  g_Vth);
    cudaGetSymbolAddress((void**)&Vtl,  g_Vtl);
    cudaGetSymbolAddress((void**)&Ph,   g_Ph);
    cudaGetSymbolAddress((void**)&Pl,   g_Pl);
    cudaGetSymbolAddress((void**)&oh,   g_oh);
    cudaGetSymbolAddress((void**)&wh,   g_wh);

    cudaFuncSetAttribute(proj_kernel, cudaFuncAttributeMaxDynamicSharedMemorySize, SMEM_NP2);
    cudaFuncSetAttribute(gemm_b<3>,   cudaFuncAttributeMaxDynamicSharedMemorySize, SMEM_NP3);
    cudaFuncSetAttribute(gemm_b<1>,   cudaFuncAttributeMaxDynamicSharedMemorySize, SMEM_NP1);

    // 0) all weight hi planes in one launch (MLP=4)
    split_all_kernel<<<(4ULL * E * E / 4) / 1024, 256>>>(in_w, out_w, wh);

    // 1) both LayerNorms in one launch
    ln_all<<<Bb * Nn + Mm, 256>>>(x, query, pos, ln_kv_w, ln_kv_b, ln_q_w, ln_q_b,
                                  kvh, kvl, kvph, kvpl, qh, ql);

    // 2) merged K/Q/V projections (256-row tiles, warp 64x64, ldmatrix)
    proj_kernel<<<dim3(32, 17, 1), 256, SMEM_NP2>>>(
        kvph, kvpl, qh, ql, kvh, kvl, wh, in_b, Kh, Kl, Qh, Ql, Vh, Vl);

    // 3) V transpose
    vtrans<<<dim3(Dd / 32, Nn / 32, Bb * Hh), 256>>>(Vh, Vl, Vth, Vtl);

    // 4) scores = Q @ K^T / sqrt(D), 3-pass
    gemm_b<3><<<dim3(2, 1, Bb * Hh), 256, SMEM_NP3>>>(
        Qh, Ql, Kh, Kl, nullptr, 0.08838834764831845f, attn, nullptr, nullptr,
        (size_t)Dd, 0, (size_t)Dd, (size_t)Nn * E,
        (size_t)Mm * Nn, 32ULL * Mm * Nn, E, E, Nn, Dd / BK);

    // 5) fused softmax + P planes + head-mean (-> d_out tail)
    softmax_mean<<<Bb * Mm, 256>>>(attn, Ph, Pl, out + (size_t)Bb * Mm * E);

    // 6) O = P @ V, 3-pass -> oh only
    gemm_b<3><<<dim3(1, 1, Bb * Hh), 256, SMEM_NP3>>>(
        Ph, Pl, Vth, Vtl, nullptr, 1.f, nullptr, oh, nullptr,
        (size_t)Mm * Nn, 32ULL * Mm * Nn, (size_t)Dd * Nn, 32ULL * Dd * Nn,
        (size_t)Dd, (size_t)Mm * E, Nn, Nn, E, Nn / BK);

    // 7) out projection -> d_out, 1-pass
    gemm_b<1><<<dim3(32, 8, 1), 256, SMEM_NP1>>>(
        oh, nullptr, wh + 3ULL * E * E, nullptr, out_b, 1.f, out, nullptr, nullptr,
        0, 0, 0, 0, 0, 0, E, E, E, E / BK);
}

// round 15
// speedup vs baseline: 1.0806x; 1.0806x over previous
#include <cuda_runtime.h>
#include <cuda_fp16.h>
#include <cstdint>
#include <math.h>

#define E  4096
#define Hh 32
#define Mm 256
#define Bb 8
#define Nn 256
#define Dd 128

// ---------------- scratch (alloc-free: __device__ globals) ----------------
__device__ float g_attn[Bb * Hh * Mm * Nn];   // fp32 scores S

// fp16 hi/lo planes
__device__ __half g_qh[Mm * E],        g_ql[Mm * E];
__device__ __half g_kvh[Bb * Nn * E],  g_kvl[Bb * Nn * E];
__device__ __half g_kvph[Bb * Nn * E], g_kvpl[Bb * Nn * E];
__device__ __half g_Qh[Mm * E],        g_Ql[Mm * E];
__device__ __half g_Kh[Bb * Nn * E],   g_Kl[Bb * Nn * E];
__device__ __half g_Vth[Bb * Hh * Dd * Nn], g_Vtl[Bb * Hh * Dd * Nn];  // V^T planes (written by proj)
__device__ __half g_Ph[Bb * Hh * Mm * Nn],  g_Pl[Bb * Hh * Mm * Nn];
__device__ __half g_oh[Bb * Mm * E];
__device__ __half g_wh[4ULL * E * E];   // Wq,Wk,Wv,Wo hi planes

// ---------------- helpers ----------------
__device__ __forceinline__ uint32_t smem_u32(const void* p) {
    uint32_t a;
    asm("{ .reg .u64 t; cvta.to.shared.u64 t, %1; cvt.u32.u64 %0, t; }"
        : "=r"(a) : "l"(p));
    return a;
}

__device__ __forceinline__ void cp_async16(uint32_t dst, const void* src) {
    asm volatile("cp.async.cg.shared.global [%0], [%1], 16;"
                 :: "r"(dst), "l"(src) : "memory");
}
#define CP_COMMIT() asm volatile("cp.async.commit_group;" ::: "memory")
#define CP_WAIT1()  asm volatile("cp.async.wait_group 1;" ::: "memory")

__device__ __forceinline__ void mma16816(float* d, const uint32_t* a, const uint32_t* b) {
    asm volatile(
        "mma.sync.aligned.m16n8k16.row.col.f32.f16.f16.f32 "
        "{%0,%1,%2,%3}, {%4,%5,%6,%7}, {%8,%9}, {%0,%1,%2,%3};"
        : "+f"(d[0]), "+f"(d[1]), "+f"(d[2]), "+f"(d[3])
        : "r"(a[0]), "r"(a[1]), "r"(a[2]), "r"(a[3]), "r"(b[0]), "r"(b[1]));
}

__device__ __forceinline__ void ldsm4(uint32_t& r0, uint32_t& r1, uint32_t& r2, uint32_t& r3,
                                      uint32_t addr) {
    asm volatile("ldmatrix.sync.aligned.m8n8.x4.shared.b16 {%0,%1,%2,%3}, [%4];"
                 : "=r"(r0), "=r"(r1), "=r"(r2), "=r"(r3) : "r"(addr));
}

__device__ __forceinline__ void split_f4(float4 v, uint2& hi, uint2& lo) {
    __half2 h0 = __floats2half2_rn(v.x, v.y);
    __half2 h1 = __floats2half2_rn(v.z, v.w);
    float2 f0 = __half22float2(h0), f1 = __half22float2(h1);
    __half2 l0 = __floats2half2_rn(v.x - f0.x, v.y - f0.y);
    __half2 l1 = __floats2half2_rn(v.z - f1.x, v.w - f1.y);
    hi.x = *(uint32_t*)&h0; hi.y = *(uint32_t*)&h1;
    lo.x = *(uint32_t*)&l0; lo.y = *(uint32_t*)&l1;
}

__device__ __forceinline__ void split2(float x, float y, uint32_t& h, uint32_t& l) {
    __half2 hh = __floats2half2_rn(x, y);
    float2 f = __half22float2(hh);
    __half2 ll = __floats2half2_rn(x - f.x, y - f.y);
    h = *(uint32_t*)&hh; l = *(uint32_t*)&ll;
}

// ---------------- merged weight split, MLP=4 ----------------
__global__ void __launch_bounds__(256) split_all_kernel(
    const float* __restrict__ in_w, const float* __restrict__ out_w,
    __half* __restrict__ wh)
{
    const size_t n_in = 3ULL * E * E / 4;
    size_t base = (size_t)blockIdx.x * 1024 + threadIdx.x;
    float4 v[4];
#pragma unroll
    for (int j = 0; j < 4; j++) {
        size_t i = base + j * 256;
        v[j] = (i < n_in) ? ((const float4*)in_w)[i]
                          : ((const float4*)out_w)[i - n_in];
    }
#pragma unroll
    for (int j = 0; j < 4; j++) {
        size_t i = base + j * 256;
        __half2 h0 = __floats2half2_rn(v[j].x, v[j].y);
        __half2 h1 = __floats2half2_rn(v[j].z, v[j].w);
        uint2 h;
        h.x = *(uint32_t*)&h0; h.y = *(uint32_t*)&h1;
        *(uint2*)(wh + i * 4) = h;
    }
}

// ---------------- merged LayerNorm ----------------
__global__ void __launch_bounds__(256) ln_all(
    const float* __restrict__ x, const float* __restrict__ query,
    const float* __restrict__ pos,
    const float* __restrict__ kv_w, const float* __restrict__ kv_b,
    const float* __restrict__ q_w,  const float* __restrict__ q_b,
    __half* __restrict__ kvh, __half* __restrict__ kvl,
    __half* __restrict__ kvph, __half* __restrict__ kvpl,
    __half* __restrict__ qh, __half* __restrict__ ql)
{
    int row = blockIdx.x;
    int tid = threadIdx.x;
    const bool isq = row >= Bb * Nn;
    int r = isq ? row - Bb * Nn : row;
    const float* src = isq ? query + (size_t)r * E : x + (size_t)r * E;
    const float* w  = isq ? q_w : kv_w;
    const float* bs = isq ? q_b : kv_b;
    __half* h0 = isq ? nullptr : kvh + (size_t)r * E;
    __half* l0 = isq ? nullptr : kvl + (size_t)r * E;
    __half* hp = (isq ? qh : kvph) + (size_t)r * E;
    __half* lp = (isq ? ql : kvpl) + (size_t)r * E;
    int prow = isq ? r : (r & (Nn - 1));

    const float4* xr = (const float4*)src;
    float4 v[4];
    float s = 0.f, sq = 0.f;
#pragma unroll
    for (int i = 0; i < 4; i++) {
        v[i] = xr[tid + 256 * i];
        s  += v[i].x + v[i].y + v[i].z + v[i].w;
        sq += v[i].x * v[i].x + v[i].y * v[i].y + v[i].z * v[i].z + v[i].w * v[i].w;
    }
    __shared__ float s1[256], s2[256];
    s1[tid] = s; s2[tid] = sq;
    __syncthreads();
    for (int st = 128; st > 0; st >>= 1) {
        if (tid < st) { s1[tid] += s1[tid + st]; s2[tid] += s2[tid + st]; }
        __syncthreads();
    }
    float mean = s1[0] * (1.f / E);
    float var  = s2[0] * (1.f / E) - mean * mean;
    float rstd = rsqrtf(var + 1e-5f);

    const float4* wr = (const float4*)w;
    const float4* br = (const float4*)bs;
    const float4* pr = (const float4*)(pos + (size_t)prow * E);
#pragma unroll
    for (int i = 0; i < 4; i++) {
        int c = tid + 256 * i;
        float4 ww = wr[c], bb = br[c];
        float4 o;
        o.x = (v[i].x - mean) * rstd * ww.x + bb.x;
        o.y = (v[i].y - mean) * rstd * ww.y + bb.y;
        o.z = (v[i].z - mean) * rstd * ww.z + bb.z;
        o.w = (v[i].w - mean) * rstd * ww.w + bb.w;
        size_t off = (size_t)c * 4;
        uint2 h, l;
        if (h0) {
            split_f4(o, h, l);
            *(uint2*)(h0 + off) = h;
            *(uint2*)(l0 + off) = l;
        }
        float4 p = pr[c];
        o.x += p.x; o.y += p.y; o.z += p.z; o.w += p.w;
        split_f4(o, h, l);
        *(uint2*)(hp + off) = h;
        *(uint2*)(lp + off) = l;
    }
}

// ======================= pipelined HMMA GEMM body, 128x128 tile, ldmatrix (R13-verified) =======================
// fp32 accumulate. NPASS=1: Ah.Bh ; 2: +Al.Bh ; 3: +Ah.Bl.
// VT: epilogue writes hi/lo planes to V^T layout [(b*32+h)][d][n] (m = global token row).
#define BK 64
#define PLANE16K 16384

template <int NPASS, bool VT>
__device__ __forceinline__ void gemm_body(
    const __half* p0, const __half* p1,
    const __half* p2, const __half* p3,
    const float* bptr, float scale,
    float* ocf, __half* och, __half* ocl, size_t cOff,
    int lda, int ldb, int ldc, int NIT, int m0, int n0, char* sm)
{
    constexpr int STAGE = (NPASS == 3) ? 4 * PLANE16K : 3 * PLANE16K;
    const uint32_t sbase = smem_u32(sm);
    const int tid  = threadIdx.x;
    const int wid  = tid >> 5;
    const int lane = tid & 31;
    const int g    = lane >> 2;
    const int tq   = lane & 3;
    const int wm   = (wid >> 1) * 32;   // 4 warps along M
    const int wn   = (wid & 1) * 64;    // 2 warps along N

    // ldmatrix per-thread address components
    const int hiA  = lane >> 4;
    uint32_t rAterm[2], rA7[2];
#pragma unroll
    for (int mt = 0; mt < 2; mt++) {
        int rowA = wm + mt * 16 + (lane & 15);
        rAterm[mt] = (uint32_t)rowA * 128;
        rA7[mt]    = (uint32_t)(rowA & 7);
    }
    const int khiB = (lane >> 3) & 1;
    uint32_t rBterm[4], rB7[4];
#pragma unroll
    for (int j = 0; j < 4; j++) {
        int rowB = wn + (2 * j + (lane >> 4)) * 8 + (lane & 7);
        rBterm[j] = (uint32_t)rowB * 128;
        rB7[j]    = (uint32_t)(rowB & 7);
    }

    float acc[2][8][4];
#pragma unroll
    for (int i = 0; i < 2; i++)
#pragma unroll
        for (int j = 0; j < 8; j++)
#pragma unroll
            for (int k = 0; k < 4; k++) acc[i][j][k] = 0.f;

    auto issue = [&](int slot, int kt) {
        uint32_t sb = sbase + slot * STAGE;
#pragma unroll
        for (int j = 0; j < 4; j++) {
            int idx = tid + 256 * j;
            int row = idx >> 3;
            int c   = idx & 7;
            uint32_t so = row * 128 + ((c ^ (row & 7)) << 4);
            cp_async16(sb + so, p0 + (size_t)row * lda + kt + c * 8);
            if (NPASS >= 2)
                cp_async16(sb + PLANE16K + so, p1 + (size_t)row * lda + kt + c * 8);
            cp_async16(sb + 2 * PLANE16K + so, p2 + (size_t)row * ldb + kt + c * 8);
            if (NPASS == 3)
                cp_async16(sb + 3 * PLANE16K + so, p3 + (size_t)row * ldb + kt + c * 8);
        }
    };

    issue(0, 0);  CP_COMMIT();
    if (NIT > 1) issue(1, BK);
    CP_COMMIT();

    for (int it = 0; it < NIT; it++) {
        CP_WAIT1();
        __syncthreads();

        const uint32_t base = sbase + (it & 1) * STAGE;
        const uint32_t AhB = base;
        const uint32_t AlB = base + PLANE16K;
        const uint32_t BhB = base + 2 * PLANE16K;
        const uint32_t BlB = base + 3 * PLANE16K;
#pragma unroll
        for (int ks = 0; ks < BK; ks += 16) {
            const uint32_t kb = (uint32_t)(ks >> 3);
            uint32_t ah[2][4], bf[8][2];
#pragma unroll
            for (int mt = 0; mt < 2; mt++)
                ldsm4(ah[mt][0], ah[mt][1], ah[mt][2], ah[mt][3],
                      AhB + rAterm[mt] + (((kb + hiA) ^ rA7[mt]) << 4));
#pragma unroll
            for (int j = 0; j < 4; j++)
                ldsm4(bf[2 * j][0], bf[2 * j][1], bf[2 * j + 1][0], bf[2 * j + 1][1],
                      BhB + rBterm[j] + (((kb + khiB) ^ rB7[j]) << 4));
#pragma unroll
            for (int mt = 0; mt < 2; mt++)
#pragma unroll
                for (int nt = 0; nt < 8; nt++) mma16816(acc[mt][nt], ah[mt], bf[nt]);
            if (NPASS >= 2) {
                uint32_t al[2][4];
#pragma unroll
                for (int mt = 0; mt < 2; mt++)
                    ldsm4(al[mt][0], al[mt][1], al[mt][2], al[mt][3],
                          AlB + rAterm[mt] + (((kb + hiA) ^ rA7[mt]) << 4));
#pragma unroll
                for (int mt = 0; mt < 2; mt++)
#pragma unroll
                    for (int nt = 0; nt < 8; nt++) mma16816(acc[mt][nt], al[mt], bf[nt]);
            }
            if (NPASS == 3) {
#pragma unroll
                for (int j = 0; j < 4; j++)
                    ldsm4(bf[2 * j][0], bf[2 * j][1], bf[2 * j + 1][0], bf[2 * j + 1][1],
                          BlB + rBterm[j] + (((kb + khiB) ^ rB7[j]) << 4));
#pragma unroll
                for (int mt = 0; mt < 2; mt++)
#pragma unroll
                    for (int nt = 0; nt < 8; nt++) mma16816(acc[mt][nt], ah[mt], bf[nt]);
            }
        }
        __syncthreads();
        if (it + 2 < NIT) issue((it + 2) & 1, (it + 2) * BK);
        CP_COMMIT();
    }

    // epilogue
    float bn[8][2];
#pragma unroll
    for (int nt = 0; nt < 8; nt++) {
        if (bptr) {
            int n = n0 + wn + nt * 8 + tq * 2;
            bn[nt][0] = bptr[n];
            bn[nt][1] = bptr[n + 1];
        } else {
            bn[nt][0] = 0.f; bn[nt][1] = 0.f;
        }
    }
#pragma unroll
    for (int mt = 0; mt < 2; mt++)
#pragma unroll
        for (int half = 0; half < 2; half++) {
            int m = m0 + wm + mt * 16 + g + half * 8;
#pragma unroll
            for (int nt = 0; nt < 8; nt++) {
                float vx = acc[mt][nt][half * 2 + 0] * scale + bn[nt][0];
                float vy = acc[mt][nt][half * 2 + 1] * scale + bn[nt][1];
                if (VT) {
                    // transposed V store: m = token row (b*256+n), col = h*128+d
                    int col = n0 + wn + nt * 8 + tq * 2;
                    int bidx = m >> 8, nn = m & 255;
                    int h = col >> 7, d = col & 127;
                    size_t dst = (((size_t)(bidx * 32 + h) * 128) + d) * 256 + nn;
                    __half hvx = __float2half_rn(vx);
                    __half hvy = __float2half_rn(vy);
                    och[dst]       = hvx;
                    och[dst + 256] = hvy;
                    ocl[dst]       = __float2half_rn(vx - __half2float(hvx));
                    ocl[dst + 256] = __float2half_rn(vy - __half2float(hvy));
                } else {
                    size_t off = cOff + (size_t)m * ldc + n0 + wn + nt * 8 + tq * 2;
                    if (ocf) *(float2*)(ocf + off) = make_float2(vx, vy);
                    if (och) {
                        uint32_t h, l;
                        split2(vx, vy, h, l);
                        *(uint32_t*)(och + off) = h;
                        if (ocl) *(uint32_t*)(ocl + off) = l;
                    }
                }
            }
        }
}

#define SMEM_NP2 (2 * 3 * PLANE16K)   // 96 KB -> 2 CTAs/SM
#define SMEM_NP3 (2 * 4 * PLANE16K)   // 128 KB -> 1 CTA/SM (small kernels)

// ---------------- merged K/Q/V projection launch ----------------
// y<16: K (2-pass); y in[16,18): Q (2-pass); y>=18: V (1-pass, writes V^T planes directly).
__global__ void __launch_bounds__(256, 2) proj_kernel(
    const __half* __restrict__ kvph, const __half* __restrict__ kvpl,
    const __half* __restrict__ qh,   const __half* __restrict__ ql,
    const __half* __restrict__ kvh,  const __half* __restrict__ kvl,
    const __half* __restrict__ wh,   const float* __restrict__ in_b,
    __half* __restrict__ Kh, __half* __restrict__ Kl,
    __half* __restrict__ Qh, __half* __restrict__ Ql,
    __half* __restrict__ Vth, __half* __restrict__ Vtl)
{
    extern __shared__ char sm[];
    const int y = blockIdx.y;
    const int n0 = blockIdx.x * 128;
    if (y < 16) {
        int m0 = y * 128;
        gemm_body<2, false>(kvph + (size_t)m0 * E, kvpl + (size_t)m0 * E,
                            wh + (size_t)E * E + (size_t)n0 * E, nullptr,
                            in_b + E, 1.f, nullptr, Kh, Kl, 0,
                            E, E, E, E / BK, m0, n0, sm);
    } else if (y < 18) {
        int m0 = (y - 16) * 128;
        gemm_body<2, false>(qh + (size_t)m0 * E, ql + (size_t)m0 * E,
                            wh + (size_t)n0 * E, nullptr,
                            in_b, 1.f, nullptr, Qh, Ql, 0,
                            E, E, E, E / BK, m0, n0, sm);
    } else {
        int m0 = (y - 18) * 128;
        gemm_body<1, true>(kvh + (size_t)m0 * E, nullptr,
                           wh + 2ULL * E * E + (size_t)n0 * E, nullptr,
                           in_b + 2 * E, 1.f, nullptr, Vth, Vtl, 0,
                           E, E, E, E / BK, m0, n0, sm);
    }
}

// ---------------- generic batched GEMM ----------------
template <int NPASS>
__global__ void __launch_bounds__(256, 2) gemm_b(
    const __half* __restrict__ Ahp, const __half* __restrict__ Alp,
    const __half* __restrict__ Bhp, const __half* __restrict__ Blp,
    const float* __restrict__ bias, float scale,
    float* __restrict__ Cf, __half* __restrict__ Ch, __half* __restrict__ Cl,
    size_t aSH, size_t aSB, size_t bSH, size_t bSB, size_t cSH, size_t cSB,
    int lda, int ldb, int ldc, int NIT)
{
    extern __shared__ char sm[];
    const int m0 = blockIdx.y * 128;
    const int n0 = blockIdx.x * 128;
    const int z  = blockIdx.z;
    const int hz = z & 31, bz = z >> 5;
    const size_t aOff = (size_t)hz * aSH + (size_t)bz * aSB;
    const size_t bOff = (size_t)hz * bSH + (size_t)bz * bSB;
    const size_t cOff = (size_t)hz * cSH + (size_t)bz * cSB;
    gemm_body<NPASS, false>(
        Ahp + aOff + (size_t)m0 * lda,
        (NPASS >= 2) ? Alp + aOff + (size_t)m0 * lda : nullptr,
        Bhp + bOff + (size_t)n0 * ldb,
        (NPASS == 3) ? Blp + bOff + (size_t)n0 * ldb : nullptr,
        bias, scale, Cf, Ch, Cl, cOff, lda, ldb, ldc, NIT, m0, n0, sm);
}

// ---------------- fused softmax + P-split + head-mean ----------------
__global__ void __launch_bounds__(256) softmax_mean(
    const float* __restrict__ attn,
    __half* __restrict__ Ph, __half* __restrict__ Pl,
    float* __restrict__ out_mean)
{
    __shared__ float red[8 * 256];
    int bm = blockIdx.x;
    int b = bm >> 8, m = bm & 255;
    int w = threadIdx.x >> 5, lane = threadIdx.x & 31;

    float ms[8];
#pragma unroll
    for (int i = 0; i < 8; i++) ms[i] = 0.f;

#pragma unroll
    for (int j = 0; j < 4; j++) {
        int h = w + j * 8;
        size_t row = ((size_t)(b * Hh + h) * Mm + m);
        const float4* p = (const float4*)(attn + row * Nn);
        float4 v0 = p[lane];
        float4 v1 = p[lane + 32];
        float mx = fmaxf(fmaxf(fmaxf(v0.x, v0.y), fmaxf(v0.z, v0.w)),
                         fmaxf(fmaxf(v1.x, v1.y), fmaxf(v1.z, v1.w)));
#pragma unroll
        for (int o = 16; o; o >>= 1) mx = fmaxf(mx, __shfl_xor_sync(0xffffffffu, mx, o));
        v0.x = expf(v0.x - mx); v0.y = expf(v0.y - mx);
        v0.z = expf(v0.z - mx); v0.w = expf(v0.w - mx);
        v1.x = expf(v1.x - mx); v1.y = expf(v1.y - mx);
        v1.z = expf(v1.z - mx); v1.w = expf(v1.w - mx);
        float s = v0.x + v0.y + v0.z + v0.w + v1.x + v1.y + v1.z + v1.w;
#pragma unroll
        for (int o = 16; o; o >>= 1) s += __shfl_xor_sync(0xffffffffu, s, o);
        float inv = 1.f / s;
        v0.x *= inv; v0.y *= inv; v0.z *= inv; v0.w *= inv;
        v1.x *= inv; v1.y *= inv; v1.z *= inv; v1.w *= inv;
        uint2 hh, ll;
        split_f4(v0, hh, ll);
        *(uint2*)(Ph + row * Nn + lane * 4) = hh;
        *(uint2*)(Pl + row * Nn + lane * 4) = ll;
        split_f4(v1, hh, ll);
        *(uint2*)(Ph + row * Nn + 128 + lane * 4) = hh;
        *(uint2*)(Pl + row * Nn + 128 + lane * 4) = ll;
        ms[0] += v0.x; ms[1] += v0.y; ms[2] += v0.z; ms[3] += v0.w;
        ms[4] += v1.x; ms[5] += v1.y; ms[6] += v1.z; ms[7] += v1.w;
    }
#pragma unroll
    for (int k = 0; k < 4; k++) red[w * 256 + lane * 4 + k]       = ms[k];
#pragma unroll
    for (int k = 0; k < 4; k++) red[w * 256 + 128 + lane * 4 + k] = ms[4 + k];
    __syncthreads();
    int n = threadIdx.x;
    float s = 0.f;
#pragma unroll
    for (int ww = 0; ww < 8; ww++) s += red[ww * 256 + n];
    out_mean[(size_t)bm * Nn + n] = s * (1.f / Hh);
}

// ---------------- launcher ----------------
extern "C" void kernel_launch(void* const* d_in, const int* in_sizes, int n_in,
                              void* d_out, int out_size)
{
    const float* x       = (const float*)d_in[0];
    const float* query   = (const float*)d_in[1];
    const float* pos     = (const float*)d_in[2];
    const float* ln_q_w  = (const float*)d_in[3];
    const float* ln_q_b  = (const float*)d_in[4];
    const float* ln_kv_w = (const float*)d_in[5];
    const float* ln_kv_b = (const float*)d_in[6];
    const float* in_w    = (const float*)d_in[7];
    const float* in_b    = (const float*)d_in[8];
    const float* out_w   = (const float*)d_in[9];
    const float* out_b   = (const float*)d_in[10];
    float* out = (float*)d_out;

    float *attn;
    cudaGetSymbolAddress((void**)&attn, g_attn);
    __half *qh, *ql, *kvh, *kvl, *kvph, *kvpl;
    __half *Qh, *Ql, *Kh, *Kl, *Vth, *Vtl, *Ph, *Pl, *oh, *wh;
    cudaGetSymbolAddress((void**)&qh,   g_qh);
    cudaGetSymbolAddress((void**)&ql,   g_ql);
    cudaGetSymbolAddress((void**)&kvh,  g_kvh);
    cudaGetSymbolAddress((void**)&kvl,  g_kvl);
    cudaGetSymbolAddress((void**)&kvph, g_kvph);
    cudaGetSymbolAddress((void**)&kvpl, g_kvpl);
    cudaGetSymbolAddress((void**)&Qh,   g_Qh);
    cudaGetSymbolAddress((void**)&Ql,   g_Ql);
    cudaGetSymbolAddress((void**)&Kh,   g_Kh);
    cudaGetSymbolAddress((void**)&Kl,   g_Kl);
    cudaGetSymbolAddress((void**)&Vth,  g_Vth);
    cudaGetSymbolAddress((void**)&Vtl,  g_Vtl);
    cudaGetSymbolAddress((void**)&Ph,   g_Ph);
    cudaGetSymbolAddress((void**)&Pl,   g_Pl);
    cudaGetSymbolAddress((void**)&oh,   g_oh);
    cudaGetSymbolAddress((void**)&wh,   g_wh);

    cudaFuncSetAttribute(proj_kernel, cudaFuncAttributeMaxDynamicSharedMemorySize, SMEM_NP2);
    cudaFuncSetAttribute(gemm_b<3>,   cudaFuncAttributeMaxDynamicSharedMemorySize, SMEM_NP3);
    cudaFuncSetAttribute(gemm_b<1>,   cudaFuncAttributeMaxDynamicSharedMemorySize, SMEM_NP2);

    // 0) all weight hi planes in one launch (MLP=4)
    split_all_kernel<<<(4ULL * E * E / 4) / 1024, 256>>>(in_w, out_w, wh);

    // 1) both LayerNorms in one launch
    ln_all<<<Bb * Nn + Mm, 256>>>(x, query, pos, ln_kv_w, ln_kv_b, ln_q_w, ln_q_b,
                                  kvh, kvl, kvph, kvpl, qh, ql);

    // 2) merged K/Q/V projections (128-row tiles, 2 CTAs/SM, ldmatrix; V writes V^T directly)
    proj_kernel<<<dim3(32, 34, 1), 256, SMEM_NP2>>>(
        kvph, kvpl, qh, ql, kvh, kvl, wh, in_b, Kh, Kl, Qh, Ql, Vth, Vtl);

    // 3) scores = Q @ K^T / sqrt(D), 3-pass
    gemm_b<3><<<dim3(2, 2, Bb * Hh), 256, SMEM_NP3>>>(
        Qh, Ql, Kh, Kl, nullptr, 0.08838834764831845f, attn, nullptr, nullptr,
        (size_t)Dd, 0, (size_t)Dd, (size_t)Nn * E,
        (size_t)Mm * Nn, 32ULL * Mm * Nn, E, E, Nn, Dd / BK);

    // 4) fused softmax + P planes + head-mean (-> d_out tail)
    softmax_mean<<<Bb * Mm, 256>>>(attn, Ph, Pl, out + (size_t)Bb * Mm * E);

    // 5) O = P @ V, 3-pass -> oh only
    gemm_b<3><<<dim3(1, 2, Bb * Hh), 256, SMEM_NP3>>>(
        Ph, Pl, Vth, Vtl, nullptr, 1.f, nullptr, oh, nullptr,
        (size_t)Mm * Nn, 32ULL * Mm * Nn, (size_t)Dd * Nn, 32ULL * Dd * Nn,
        (size_t)Dd, (size_t)Mm * E, Nn, Nn, E, Nn / BK);

    // 6) out projection -> d_out, 1-pass
    gemm_b<1><<<dim3(32, 16, 1), 256, SMEM_NP2>>>(
        oh, nullptr, wh + 3ULL * E * E, nullptr, out_b, 1.f, out, nullptr, nullptr,
        0, 0, 0, 0, 0, 0, E, E, E, E / BK);
}

// round 16
// speedup vs baseline: 1.0906x; 1.0092x over previous
#include <cuda_runtime.h>
#include <cuda_fp16.h>
#include <cstdint>
#include <math.h>

#define E  4096
#define Hh 32
#define Mm 256
#define Bb 8
#define Nn 256
#define Dd 128

// ---------------- scratch (alloc-free: __device__ globals) ----------------
__device__ float g_attn[Bb * Hh * Mm * Nn];   // fp32 scores S

// fp16 hi/lo planes
__device__ __half g_qh[Mm * E],        g_ql[Mm * E];
__device__ __half g_kvh[Bb * Nn * E],  g_kvl[Bb * Nn * E];
__device__ __half g_kvph[Bb * Nn * E], g_kvpl[Bb * Nn * E];
__device__ __half g_Qh[Mm * E],        g_Ql[Mm * E];
__device__ __half g_Kh[Bb * Nn * E],   g_Kl[Bb * Nn * E];
__device__ __half g_Vth[Bb * Hh * Dd * Nn], g_Vtl[Bb * Hh * Dd * Nn];  // V^T planes (written by proj)
__device__ __half g_Ph[Bb * Hh * Mm * Nn],  g_Pl[Bb * Hh * Mm * Nn];
__device__ __half g_oh[Bb * Mm * E];
__device__ __half g_wh[4ULL * E * E];   // Wq,Wk,Wv,Wo hi planes

// ---------------- helpers ----------------
__device__ __forceinline__ uint32_t smem_u32(const void* p) {
    uint32_t a;
    asm("{ .reg .u64 t; cvta.to.shared.u64 t, %1; cvt.u32.u64 %0, t; }"
        : "=r"(a) : "l"(p));
    return a;
}

__device__ __forceinline__ void cp_async16(uint32_t dst, const void* src) {
    asm volatile("cp.async.cg.shared.global [%0], [%1], 16;"
                 :: "r"(dst), "l"(src) : "memory");
}
#define CP_COMMIT() asm volatile("cp.async.commit_group;" ::: "memory")
#define CP_WAIT1()  asm volatile("cp.async.wait_group 1;" ::: "memory")

__device__ __forceinline__ void mma16816(float* d, const uint32_t* a, const uint32_t* b) {
    asm volatile(
        "mma.sync.aligned.m16n8k16.row.col.f32.f16.f16.f32 "
        "{%0,%1,%2,%3}, {%4,%5,%6,%7}, {%8,%9}, {%0,%1,%2,%3};"
        : "+f"(d[0]), "+f"(d[1]), "+f"(d[2]), "+f"(d[3])
        : "r"(a[0]), "r"(a[1]), "r"(a[2]), "r"(a[3]), "r"(b[0]), "r"(b[1]));
}

__device__ __forceinline__ void ldsm4(uint32_t& r0, uint32_t& r1, uint32_t& r2, uint32_t& r3,
                                      uint32_t addr) {
    asm volatile("ldmatrix.sync.aligned.m8n8.x4.shared.b16 {%0,%1,%2,%3}, [%4];"
                 : "=r"(r0), "=r"(r1), "=r"(r2), "=r"(r3) : "r"(addr));
}

__device__ __forceinline__ void split_f4(float4 v, uint2& hi, uint2& lo) {
    __half2 h0 = __floats2half2_rn(v.x, v.y);
    __half2 h1 = __floats2half2_rn(v.z, v.w);
    float2 f0 = __half22float2(h0), f1 = __half22float2(h1);
    __half2 l0 = __floats2half2_rn(v.x - f0.x, v.y - f0.y);
    __half2 l1 = __floats2half2_rn(v.z - f1.x, v.w - f1.y);
    hi.x = *(uint32_t*)&h0; hi.y = *(uint32_t*)&h1;
    lo.x = *(uint32_t*)&l0; lo.y = *(uint32_t*)&l1;
}

__device__ __forceinline__ void split2(float x, float y, uint32_t& h, uint32_t& l) {
    __half2 hh = __floats2half2_rn(x, y);
    float2 f = __half22float2(hh);
    __half2 ll = __floats2half2_rn(x - f.x, y - f.y);
    h = *(uint32_t*)&hh; l = *(uint32_t*)&ll;
}

// ---------------- merged weight split, MLP=4 ----------------
__global__ void __launch_bounds__(256) split_all_kernel(
    const float* __restrict__ in_w, const float* __restrict__ out_w,
    __half* __restrict__ wh)
{
    const size_t n_in = 3ULL * E * E / 4;
    size_t base = (size_t)blockIdx.x * 1024 + threadIdx.x;
    float4 v[4];
#pragma unroll
    for (int j = 0; j < 4; j++) {
        size_t i = base + j * 256;
        v[j] = (i < n_in) ? ((const float4*)in_w)[i]
                          : ((const float4*)out_w)[i - n_in];
    }
#pragma unroll
    for (int j = 0; j < 4; j++) {
        size_t i = base + j * 256;
        __half2 h0 = __floats2half2_rn(v[j].x, v[j].y);
        __half2 h1 = __floats2half2_rn(v[j].z, v[j].w);
        uint2 h;
        h.x = *(uint32_t*)&h0; h.y = *(uint32_t*)&h1;
        *(uint2*)(wh + i * 4) = h;
    }
}

// ---------------- merged LayerNorm ----------------
__global__ void __launch_bounds__(256) ln_all(
    const float* __restrict__ x, const float* __restrict__ query,
    const float* __restrict__ pos,
    const float* __restrict__ kv_w, const float* __restrict__ kv_b,
    const float* __restrict__ q_w,  const float* __restrict__ q_b,
    __half* __restrict__ kvh, __half* __restrict__ kvl,
    __half* __restrict__ kvph, __half* __restrict__ kvpl,
    __half* __restrict__ qh, __half* __restrict__ ql)
{
    int row = blockIdx.x;
    int tid = threadIdx.x;
    const bool isq = row >= Bb * Nn;
    int r = isq ? row - Bb * Nn : row;
    const float* src = isq ? query + (size_t)r * E : x + (size_t)r * E;
    const float* w  = isq ? q_w : kv_w;
    const float* bs = isq ? q_b : kv_b;
    __half* h0 = isq ? nullptr : kvh + (size_t)r * E;
    __half* l0 = isq ? nullptr : kvl + (size_t)r * E;
    __half* hp = (isq ? qh : kvph) + (size_t)r * E;
    __half* lp = (isq ? ql : kvpl) + (size_t)r * E;
    int prow = isq ? r : (r & (Nn - 1));

    const float4* xr = (const float4*)src;
    float4 v[4];
    float s = 0.f, sq = 0.f;
#pragma unroll
    for (int i = 0; i < 4; i++) {
        v[i] = xr[tid + 256 * i];
        s  += v[i].x + v[i].y + v[i].z + v[i].w;
        sq += v[i].x * v[i].x + v[i].y * v[i].y + v[i].z * v[i].z + v[i].w * v[i].w;
    }
    __shared__ float s1[256], s2[256];
    s1[tid] = s; s2[tid] = sq;
    __syncthreads();
    for (int st = 128; st > 0; st >>= 1) {
        if (tid < st) { s1[tid] += s1[tid + st]; s2[tid] += s2[tid + st]; }
        __syncthreads();
    }
    float mean = s1[0] * (1.f / E);
    float var  = s2[0] * (1.f / E) - mean * mean;
    float rstd = rsqrtf(var + 1e-5f);

    const float4* wr = (const float4*)w;
    const float4* br = (const float4*)bs;
    const float4* pr = (const float4*)(pos + (size_t)prow * E);
#pragma unroll
    for (int i = 0; i < 4; i++) {
        int c = tid + 256 * i;
        float4 ww = wr[c], bb = br[c];
        float4 o;
        o.x = (v[i].x - mean) * rstd * ww.x + bb.x;
        o.y = (v[i].y - mean) * rstd * ww.y + bb.y;
        o.z = (v[i].z - mean) * rstd * ww.z + bb.z;
        o.w = (v[i].w - mean) * rstd * ww.w + bb.w;
        size_t off = (size_t)c * 4;
        uint2 h, l;
        if (h0) {
            split_f4(o, h, l);
            *(uint2*)(h0 + off) = h;
            *(uint2*)(l0 + off) = l;
        }
        float4 p = pr[c];
        o.x += p.x; o.y += p.y; o.z += p.z; o.w += p.w;
        split_f4(o, h, l);
        *(uint2*)(hp + off) = h;
        *(uint2*)(lp + off) = l;
    }
}

// ======================= pipelined HMMA GEMM body, 128x128 tile, ldmatrix (R13-verified) =======================
// fp32 accumulate. NPASS=1: Ah.Bh ; 2: +Al.Bh ; 3: +Ah.Bl.
// Stage: Ah(16K) [+Al(16K)] Bh(16K) [+Bl(16K)]. 2 stages.
#define BK 64
#define PLANE16K 16384

template <int NPASS, bool VT>
__device__ __forceinline__ void gemm_body(
    const __half* p0, const __half* p1,
    const __half* p2, const __half* p3,
    const float* bptr, float scale,
    float* ocf, __half* och, __half* ocl, size_t cOff,
    int lda, int ldb, int ldc, int NIT, int m0, int n0, char* sm)
{
    constexpr uint32_t BOFF  = (NPASS >= 2) ? 2 * PLANE16K : PLANE16K;
    constexpr uint32_t STAGE = BOFF + ((NPASS == 3) ? 2 * PLANE16K : PLANE16K);
    const uint32_t sbase = smem_u32(sm);
    const int tid  = threadIdx.x;
    const int wid  = tid >> 5;
    const int lane = tid & 31;
    const int g    = lane >> 2;
    const int tq   = lane & 3;
    const int wm   = (wid >> 1) * 32;
    const int wn   = (wid & 1) * 64;

    const int hiA  = lane >> 4;
    uint32_t rAterm[2], rA7[2];
#pragma unroll
    for (int mt = 0; mt < 2; mt++) {
        int rowA = wm + mt * 16 + (lane & 15);
        rAterm[mt] = (uint32_t)rowA * 128;
        rA7[mt]    = (uint32_t)(rowA & 7);
    }
    const int khiB = (lane >> 3) & 1;
    uint32_t rBterm[4], rB7[4];
#pragma unroll
    for (int j = 0; j < 4; j++) {
        int rowB = wn + (2 * j + (lane >> 4)) * 8 + (lane & 7);
        rBterm[j] = (uint32_t)rowB * 128;
        rB7[j]    = (uint32_t)(rowB & 7);
    }

    float acc[2][8][4];
#pragma unroll
    for (int i = 0; i < 2; i++)
#pragma unroll
        for (int j = 0; j < 8; j++)
#pragma unroll
            for (int k = 0; k < 4; k++) acc[i][j][k] = 0.f;

    auto issue = [&](int slot, int kt) {
        uint32_t sb = sbase + slot * STAGE;
#pragma unroll
        for (int j = 0; j < 4; j++) {
            int idx = tid + 256 * j;
            int row = idx >> 3;
            int c   = idx & 7;
            uint32_t so = row * 128 + ((c ^ (row & 7)) << 4);
            cp_async16(sb + so, p0 + (size_t)row * lda + kt + c * 8);
            if (NPASS >= 2)
                cp_async16(sb + PLANE16K + so, p1 + (size_t)row * lda + kt + c * 8);
            cp_async16(sb + BOFF + so, p2 + (size_t)row * ldb + kt + c * 8);
            if (NPASS == 3)
                cp_async16(sb + BOFF + PLANE16K + so, p3 + (size_t)row * ldb + kt + c * 8);
        }
    };

    issue(0, 0);  CP_COMMIT();
    if (NIT > 1) issue(1, BK);
    CP_COMMIT();

    for (int it = 0; it < NIT; it++) {
        CP_WAIT1();
        __syncthreads();

        const uint32_t base = sbase + (it & 1) * STAGE;
        const uint32_t AhB = base;
        const uint32_t AlB = base + PLANE16K;
        const uint32_t BhB = base + BOFF;
        const uint32_t BlB = base + BOFF + PLANE16K;
#pragma unroll
        for (int ks = 0; ks < BK; ks += 16) {
            const uint32_t kb = (uint32_t)(ks >> 3);
            uint32_t ah[2][4], bf[8][2];
#pragma unroll
            for (int mt = 0; mt < 2; mt++)
                ldsm4(ah[mt][0], ah[mt][1], ah[mt][2], ah[mt][3],
                      AhB + rAterm[mt] + (((kb + hiA) ^ rA7[mt]) << 4));
#pragma unroll
            for (int j = 0; j < 4; j++)
                ldsm4(bf[2 * j][0], bf[2 * j][1], bf[2 * j + 1][0], bf[2 * j + 1][1],
                      BhB + rBterm[j] + (((kb + khiB) ^ rB7[j]) << 4));
#pragma unroll
            for (int mt = 0; mt < 2; mt++)
#pragma unroll
                for (int nt = 0; nt < 8; nt++) mma16816(acc[mt][nt], ah[mt], bf[nt]);
            if (NPASS >= 2) {
                uint32_t al[2][4];
#pragma unroll
                for (int mt = 0; mt < 2; mt++)
                    ldsm4(al[mt][0], al[mt][1], al[mt][2], al[mt][3],
                          AlB + rAterm[mt] + (((kb + hiA) ^ rA7[mt]) << 4));
#pragma unroll
                for (int mt = 0; mt < 2; mt++)
#pragma unroll
                    for (int nt = 0; nt < 8; nt++) mma16816(acc[mt][nt], al[mt], bf[nt]);
            }
            if (NPASS == 3) {
#pragma unroll
                for (int j = 0; j < 4; j++)
                    ldsm4(bf[2 * j][0], bf[2 * j][1], bf[2 * j + 1][0], bf[2 * j + 1][1],
                          BlB + rBterm[j] + (((kb + khiB) ^ rB7[j]) << 4));
#pragma unroll
                for (int mt = 0; mt < 2; mt++)
#pragma unroll
                    for (int nt = 0; nt < 8; nt++) mma16816(acc[mt][nt], ah[mt], bf[nt]);
            }
        }
        __syncthreads();
        if (it + 2 < NIT) issue((it + 2) & 1, (it + 2) * BK);
        CP_COMMIT();
    }

    // epilogue
    float bn[8][2];
#pragma unroll
    for (int nt = 0; nt < 8; nt++) {
        if (bptr) {
            int n = n0 + wn + nt * 8 + tq * 2;
            bn[nt][0] = bptr[n];
            bn[nt][1] = bptr[n + 1];
        } else {
            bn[nt][0] = 0.f; bn[nt][1] = 0.f;
        }
    }
#pragma unroll
    for (int mt = 0; mt < 2; mt++)
#pragma unroll
        for (int half = 0; half < 2; half++) {
            int m = m0 + wm + mt * 16 + g + half * 8;
#pragma unroll
            for (int nt = 0; nt < 8; nt++) {
                float vx = acc[mt][nt][half * 2 + 0] * scale + bn[nt][0];
                float vy = acc[mt][nt][half * 2 + 1] * scale + bn[nt][1];
                if (VT) {
                    int col = n0 + wn + nt * 8 + tq * 2;
                    int bidx = m >> 8, nn = m & 255;
                    int h = col >> 7, d = col & 127;
                    size_t dst = (((size_t)(bidx * 32 + h) * 128) + d) * 256 + nn;
                    __half hvx = __float2half_rn(vx);
                    __half hvy = __float2half_rn(vy);
                    och[dst]       = hvx;
                    och[dst + 256] = hvy;
                    ocl[dst]       = __float2half_rn(vx - __half2float(hvx));
                    ocl[dst + 256] = __float2half_rn(vy - __half2float(hvy));
                } else {
                    size_t off = cOff + (size_t)m * ldc + n0 + wn + nt * 8 + tq * 2;
                    if (ocf) *(float2*)(ocf + off) = make_float2(vx, vy);
                    if (och) {
                        uint32_t h, l;
                        split2(vx, vy, h, l);
                        *(uint32_t*)(och + off) = h;
                        if (ocl) *(uint32_t*)(ocl + off) = l;
                    }
                }
            }
        }
}

#define SMEM_NP1 (2 * 2 * PLANE16K)   //  64 KB
#define SMEM_NP2 (2 * 3 * PLANE16K)   //  96 KB -> 2 CTAs/SM
#define SMEM_NP3 (2 * 4 * PLANE16K)   // 128 KB -> 1 CTA/SM

// ---------------- merged K/Q/V projection launch ----------------
__global__ void __launch_bounds__(256, 2) proj_kernel(
    const __half* __restrict__ kvph, const __half* __restrict__ kvpl,
    const __half* __restrict__ qh,   const __half* __restrict__ ql,
    const __half* __restrict__ kvh,  const __half* __restrict__ kvl,
    const __half* __restrict__ wh,   const float* __restrict__ in_b,
    __half* __restrict__ Kh, __half* __restrict__ Kl,
    __half* __restrict__ Qh, __half* __restrict__ Ql,
    __half* __restrict__ Vth, __half* __restrict__ Vtl)
{
    extern __shared__ char sm[];
    const int y = blockIdx.y;
    const int n0 = blockIdx.x * 128;
    if (y < 16) {
        int m0 = y * 128;
        gemm_body<2, false>(kvph + (size_t)m0 * E, kvpl + (size_t)m0 * E,
                            wh + (size_t)E * E + (size_t)n0 * E, nullptr,
                            in_b + E, 1.f, nullptr, Kh, Kl, 0,
                            E, E, E, E / BK, m0, n0, sm);
    } else if (y < 18) {
        int m0 = (y - 16) * 128;
        gemm_body<2, false>(qh + (size_t)m0 * E, ql + (size_t)m0 * E,
                            wh + (size_t)n0 * E, nullptr,
                            in_b, 1.f, nullptr, Qh, Ql, 0,
                            E, E, E, E / BK, m0, n0, sm);
    } else {
        int m0 = (y - 18) * 128;
        gemm_body<1, true>(kvh + (size_t)m0 * E, nullptr,
                           wh + 2ULL * E * E + (size_t)n0 * E, nullptr,
                           in_b + 2 * E, 1.f, nullptr, Vth, Vtl, 0,
                           E, E, E, E / BK, m0, n0, sm);
    }
}

// ---------------- generic batched GEMM ----------------
template <int NPASS>
__global__ void __launch_bounds__(256, 2) gemm_b(
    const __half* __restrict__ Ahp, const __half* __restrict__ Alp,
    const __half* __restrict__ Bhp, const __half* __restrict__ Blp,
    const float* __restrict__ bias, float scale,
    float* __restrict__ Cf, __half* __restrict__ Ch, __half* __restrict__ Cl,
    size_t aSH, size_t aSB, size_t bSH, size_t bSB, size_t cSH, size_t cSB,
    int lda, int ldb, int ldc, int NIT)
{
    extern __shared__ char sm[];
    const int m0 = blockIdx.y * 128;
    const int n0 = blockIdx.x * 128;
    const int z  = blockIdx.z;
    const int hz = z & 31, bz = z >> 5;
    const size_t aOff = (size_t)hz * aSH + (size_t)bz * aSB;
    const size_t bOff = (size_t)hz * bSH + (size_t)bz * bSB;
    const size_t cOff = (size_t)hz * cSH + (size_t)bz * cSB;
    gemm_body<NPASS, false>(
        Ahp + aOff + (size_t)m0 * lda,
        (NPASS >= 2) ? Alp + aOff + (size_t)m0 * lda : nullptr,
        Bhp + bOff + (size_t)n0 * ldb,
        (NPASS == 3) ? Blp + bOff + (size_t)n0 * ldb : nullptr,
        bias, scale, Cf, Ch, Cl, cOff, lda, ldb, ldc, NIT, m0, n0, sm);
}

// ---------------- scores kernel: Q tile reused across all 8 batches ----------------
// grid (2, 2, 32): x = n-tile, y = m-tile, z = head. Per CTA: load Q chunks once
// (both K-halves into the two stages), stream K[b] hi/lo for b=0..7, write S_b.
__global__ void __launch_bounds__(256, 1) scores_kernel(
    const __half* __restrict__ Qh, const __half* __restrict__ Ql,
    const __half* __restrict__ Kh, const __half* __restrict__ Kl,
    float* __restrict__ attn)
{
    extern __shared__ char sm[];
    constexpr uint32_t STAGE = 4 * PLANE16K;   // Ah,Al,Bh,Bl
    const uint32_t sbase = smem_u32(sm);
    const int tid  = threadIdx.x;
    const int wid  = tid >> 5;
    const int lane = tid & 31;
    const int g    = lane >> 2;
    const int tq   = lane & 3;
    const int wm   = (wid >> 1) * 32;
    const int wn   = (wid & 1) * 64;
    const int n0 = blockIdx.x * 128;
    const int m0 = blockIdx.y * 128;
    const int h  = blockIdx.z;

    const __half* pQh = Qh + (size_t)m0 * E + h * Dd;
    const __half* pQl = Ql + (size_t)m0 * E + h * Dd;
    const __half* pKh0 = Kh + (size_t)n0 * E + h * Dd;
    const __half* pKl0 = Kl + (size_t)n0 * E + h * Dd;

    const int hiA  = lane >> 4;
    uint32_t rAterm[2], rA7[2];
#pragma unroll
    for (int mt = 0; mt < 2; mt++) {
        int rowA = wm + mt * 16 + (lane & 15);
        rAterm[mt] = (uint32_t)rowA * 128;
        rA7[mt]    = (uint32_t)(rowA & 7);
    }
    const int khiB = (lane >> 3) & 1;
    uint32_t rBterm[4], rB7[4];
#pragma unroll
    for (int j = 0; j < 4; j++) {
        int rowB = wn + (2 * j + (lane >> 4)) * 8 + (lane & 7);
        rBterm[j] = (uint32_t)rowB * 128;
        rB7[j]    = (uint32_t)(rowB & 7);
    }

    auto issueA = [&](int slot, int kt) {
        uint32_t sb = sbase + slot * STAGE;
#pragma unroll
        for (int j = 0; j < 4; j++) {
            int idx = tid + 256 * j;
            int row = idx >> 3;
            int c   = idx & 7;
            uint32_t so = row * 128 + ((c ^ (row & 7)) << 4);
            cp_async16(sb + so, pQh + (size_t)row * E + kt + c * 8);
            cp_async16(sb + PLANE16K + so, pQl + (size_t)row * E + kt + c * 8);
        }
    };
    auto issueB = [&](int slot, int b, int kt) {
        uint32_t sb = sbase + slot * STAGE;
        const __half* ph = pKh0 + (size_t)b * Nn * E + kt;
        const __half* pl = pKl0 + (size_t)b * Nn * E + kt;
#pragma unroll
        for (int j = 0; j < 4; j++) {
            int idx = tid + 256 * j;
            int row = idx >> 3;
            int c   = idx & 7;
            uint32_t so = row * 128 + ((c ^ (row & 7)) << 4);
            cp_async16(sb + 2 * PLANE16K + so, ph + (size_t)row * E + c * 8);
            cp_async16(sb + 3 * PLANE16K + so, pl + (size_t)row * E + c * 8);
        }
    };

    issueA(0, 0);  issueB(0, 0, 0);  CP_COMMIT();
    issueA(1, BK); issueB(1, 0, BK); CP_COMMIT();

    float acc[2][8][4];
#pragma unroll
    for (int i = 0; i < 2; i++)
#pragma unroll
        for (int j = 0; j < 8; j++)
#pragma unroll
            for (int k = 0; k < 4; k++) acc[i][j][k] = 0.f;

    const float scl = 0.08838834764831845f;   // 1/sqrt(128)

    for (int b = 0; b < Bb; b++) {
#pragma unroll
        for (int half = 0; half < 2; half++) {
            CP_WAIT1();
            __syncthreads();

            const uint32_t base = sbase + half * STAGE;
            const uint32_t AhB = base;
            const uint32_t AlB = base + PLANE16K;
            const uint32_t BhB = base + 2 * PLANE16K;
            const uint32_t BlB = base + 3 * PLANE16K;
#pragma unroll
            for (int ks = 0; ks < BK; ks += 16) {
                const uint32_t kb = (uint32_t)(ks >> 3);
                uint32_t ah[2][4], bf[8][2];
#pragma unroll
                for (int mt = 0; mt < 2; mt++)
                    ldsm4(ah[mt][0], ah[mt][1], ah[mt][2], ah[mt][3],
                          AhB + rAterm[mt] + (((kb + hiA) ^ rA7[mt]) << 4));
#pragma unroll
                for (int j = 0; j < 4; j++)
                    ldsm4(bf[2 * j][0], bf[2 * j][1], bf[2 * j + 1][0], bf[2 * j + 1][1],
                          BhB + rBterm[j] + (((kb + khiB) ^ rB7[j]) << 4));
#pragma unroll
                for (int mt = 0; mt < 2; mt++)
#pragma unroll
                    for (int nt = 0; nt < 8; nt++) mma16816(acc[mt][nt], ah[mt], bf[nt]);
                {
                    uint32_t al[2][4];
#pragma unroll
                    for (int mt = 0; mt < 2; mt++)
                        ldsm4(al[mt][0], al[mt][1], al[mt][2], al[mt][3],
                              AlB + rAterm[mt] + (((kb + hiA) ^ rA7[mt]) << 4));
#pragma unroll
                    for (int mt = 0; mt < 2; mt++)
#pragma unroll
                        for (int nt = 0; nt < 8; nt++) mma16816(acc[mt][nt], al[mt], bf[nt]);
                }
#pragma unroll
                for (int j = 0; j < 4; j++)
                    ldsm4(bf[2 * j][0], bf[2 * j][1], bf[2 * j + 1][0], bf[2 * j + 1][1],
                          BlB + rBterm[j] + (((kb + khiB) ^ rB7[j]) << 4));
#pragma unroll
                for (int mt = 0; mt < 2; mt++)
#pragma unroll
                    for (int nt = 0; nt < 8; nt++) mma16816(acc[mt][nt], ah[mt], bf[nt]);
            }
            __syncthreads();
            if (b + 1 < Bb) issueB(half, b + 1, half * BK);
            CP_COMMIT();
        }

        // epilogue for batch b: S[b][h][m][n], then reset acc
        float* Sb = attn + ((size_t)(b * Hh + h) * Mm + m0) * Nn + n0;
#pragma unroll
        for (int mt = 0; mt < 2; mt++)
#pragma unroll
            for (int half = 0; half < 2; half++) {
                int mrel = wm + mt * 16 + g + half * 8;
#pragma unroll
                for (int nt = 0; nt < 8; nt++) {
                    float2 v;
                    v.x = acc[mt][nt][half * 2 + 0] * scl;
                    v.y = acc[mt][nt][half * 2 + 1] * scl;
                    *(float2*)(Sb + (size_t)mrel * Nn + wn + nt * 8 + tq * 2) = v;
                }
            }
#pragma unroll
        for (int i = 0; i < 2; i++)
#pragma unroll
            for (int j = 0; j < 8; j++)
#pragma unroll
                for (int k = 0; k < 4; k++) acc[i][j][k] = 0.f;
    }
}

// ---------------- fused softmax + P-split + head-mean ----------------
__global__ void __launch_bounds__(256) softmax_mean(
    const float* __restrict__ attn,
    __half* __restrict__ Ph, __half* __restrict__ Pl,
    float* __restrict__ out_mean)
{
    __shared__ float red[8 * 256];
    int bm = blockIdx.x;
    int b = bm >> 8, m = bm & 255;
    int w = threadIdx.x >> 5, lane = threadIdx.x & 31;

    float ms[8];
#pragma unroll
    for (int i = 0; i < 8; i++) ms[i] = 0.f;

#pragma unroll
    for (int j = 0; j < 4; j++) {
        int h = w + j * 8;
        size_t row = ((size_t)(b * Hh + h) * Mm + m);
        const float4* p = (const float4*)(attn + row * Nn);
        float4 v0 = p[lane];
        float4 v1 = p[lane + 32];
        float mx = fmaxf(fmaxf(fmaxf(v0.x, v0.y), fmaxf(v0.z, v0.w)),
                         fmaxf(fmaxf(v1.x, v1.y), fmaxf(v1.z, v1.w)));
#pragma unroll
        for (int o = 16; o; o >>= 1) mx = fmaxf(mx, __shfl_xor_sync(0xffffffffu, mx, o));
        v0.x = expf(v0.x - mx); v0.y = expf(v0.y - mx);
        v0.z = expf(v0.z - mx); v0.w = expf(v0.w - mx);
        v1.x = expf(v1.x - mx); v1.y = expf(v1.y - mx);
        v1.z = expf(v1.z - mx); v1.w = expf(v1.w - mx);
        float s = v0.x + v0.y + v0.z + v0.w + v1.x + v1.y + v1.z + v1.w;
#pragma unroll
        for (int o = 16; o; o >>= 1) s += __shfl_xor_sync(0xffffffffu, s, o);
        float inv = 1.f / s;
        v0.x *= inv; v0.y *= inv; v0.z *= inv; v0.w *= inv;
        v1.x *= inv; v1.y *= inv; v1.z *= inv; v1.w *= inv;
        uint2 hh, ll;
        split_f4(v0, hh, ll);
        *(uint2*)(Ph + row * Nn + lane * 4) = hh;
        *(uint2*)(Pl + row * Nn + lane * 4) = ll;
        split_f4(v1, hh, ll);
        *(uint2*)(Ph + row * Nn + 128 + lane * 4) = hh;
        *(uint2*)(Pl + row * Nn + 128 + lane * 4) = ll;
        ms[0] += v0.x; ms[1] += v0.y; ms[2] += v0.z; ms[3] += v0.w;
        ms[4] += v1.x; ms[5] += v1.y; ms[6] += v1.z; ms[7] += v1.w;
    }
#pragma unroll
    for (int k = 0; k < 4; k++) red[w * 256 + lane * 4 + k]       = ms[k];
#pragma unroll
    for (int k = 0; k < 4; k++) red[w * 256 + 128 + lane * 4 + k] = ms[4 + k];
    __syncthreads();
    int n = threadIdx.x;
    float s = 0.f;
#pragma unroll
    for (int ww = 0; ww < 8; ww++) s += red[ww * 256 + n];
    out_mean[(size_t)bm * Nn + n] = s * (1.f / Hh);
}

// ---------------- launcher ----------------
extern "C" void kernel_launch(void* const* d_in, const int* in_sizes, int n_in,
                              void* d_out, int out_size)
{
    const float* x       = (const float*)d_in[0];
    const float* query   = (const float*)d_in[1];
    const float* pos     = (const float*)d_in[2];
    const float* ln_q_w  = (const float*)d_in[3];
    const float* ln_q_b  = (const float*)d_in[4];
    const float* ln_kv_w = (const float*)d_in[5];
    const float* ln_kv_b = (const float*)d_in[6];
    const float* in_w    = (const float*)d_in[7];
    const float* in_b    = (const float*)d_in[8];
    const float* out_w   = (const float*)d_in[9];
    const float* out_b   = (const float*)d_in[10];
    float* out = (float*)d_out;

    float *attn;
    cudaGetSymbolAddress((void**)&attn, g_attn);
    __half *qh, *ql, *kvh, *kvl, *kvph, *kvpl;
    __half *Qh, *Ql, *Kh, *Kl, *Vth, *Vtl, *Ph, *Pl, *oh, *wh;
    cudaGetSymbolAddress((void**)&qh,   g_qh);
    cudaGetSymbolAddress((void**)&ql,   g_ql);
    cudaGetSymbolAddress((void**)&kvh,  g_kvh);
    cudaGetSymbolAddress((void**)&kvl,  g_kvl);
    cudaGetSymbolAddress((void**)&kvph, g_kvph);
    cudaGetSymbolAddress((void**)&kvpl, g_kvpl);
    cudaGetSymbolAddress((void**)&Qh,   g_Qh);
    cudaGetSymbolAddress((void**)&Ql,   g_Ql);
    cudaGetSymbolAddress((void**)&Kh,   g_Kh);
    cudaGetSymbolAddress((void**)&Kl,   g_Kl);
    cudaGetSymbolAddress((void**)&Vth,  g_Vth);
    cudaGetSymbolAddress((void**)&Vtl,  g_Vtl);
    cudaGetSymbolAddress((void**)&Ph,   g_Ph);
    cudaGetSymbolAddress((void**)&Pl,   g_Pl);
    cudaGetSymbolAddress((void**)&oh,   g_oh);
    cudaGetSymbolAddress((void**)&wh,   g_wh);

    cudaFuncSetAttribute(proj_kernel,   cudaFuncAttributeMaxDynamicSharedMemorySize, SMEM_NP2);
    cudaFuncSetAttribute(scores_kernel, cudaFuncAttributeMaxDynamicSharedMemorySize, SMEM_NP3);
    cudaFuncSetAttribute(gemm_b<3>,     cudaFuncAttributeMaxDynamicSharedMemorySize, SMEM_NP3);
    cudaFuncSetAttribute(gemm_b<1>,     cudaFuncAttributeMaxDynamicSharedMemorySize, SMEM_NP1);

    // 0) all weight hi planes in one launch (MLP=4)
    split_all_kernel<<<(4ULL * E * E / 4) / 1024, 256>>>(in_w, out_w, wh);

    // 1) both LayerNorms in one launch
    ln_all<<<Bb * Nn + Mm, 256>>>(x, query, pos, ln_kv_w, ln_kv_b, ln_q_w, ln_q_b,
                                  kvh, kvl, kvph, kvpl, qh, ql);

    // 2) merged K/Q/V projections (V writes V^T directly)
    proj_kernel<<<dim3(32, 34, 1), 256, SMEM_NP2>>>(
        kvph, kvpl, qh, ql, kvh, kvl, wh, in_b, Kh, Kl, Qh, Ql, Vth, Vtl);

    // 3) scores = Q @ K^T / sqrt(D): Q reused across 8 batches, single wave
    scores_kernel<<<dim3(2, 2, Hh), 256, SMEM_NP3>>>(Qh, Ql, Kh, Kl, attn);

    // 4) fused softmax + P planes + head-mean (-> d_out tail)
    softmax_mean<<<Bb * Mm, 256>>>(attn, Ph, Pl, out + (size_t)Bb * Mm * E);

    // 5) O = P @ V, 3-pass -> oh only
    gemm_b<3><<<dim3(1, 2, Bb * Hh), 256, SMEM_NP3>>>(
        Ph, Pl, Vth, Vtl, nullptr, 1.f, nullptr, oh, nullptr,
        (size_t)Mm * Nn, 32ULL * Mm * Nn, (size_t)Dd * Nn, 32ULL * Dd * Nn,
        (size_t)Dd, (size_t)Mm * E, Nn, Nn, E, Nn / BK);

    // 6) out projection -> d_out, 1-pass
    gemm_b<1><<<dim3(32, 16, 1), 256, SMEM_NP1>>>(
        oh, nullptr, wh + 3ULL * E * E, nullptr, out_b, 1.f, out, nullptr, nullptr,
        0, 0, 0, 0, 0, 0, E, E, E, E / BK);
}